// round 7
// baseline (speedup 1.0000x reference)
#include <cuda_runtime.h>
#include <math.h>
#include <float.h>

#define NSIG   8192
#define NTHR   512
#define NWARPS 16
#define SR_INV (1.0f / 30.0f)
#define CQ   0.70710678118654752f   // cos(pi/4)
#define C8F  0.92387953251128676f   // cos(pi/8)
#define S8F  0.38268343236508977f   // sin(pi/8)

__device__ __forceinline__ int brev13(int x) { return (int)(__brev((unsigned)x) >> 19); }
// padded smem index: +1 float2 per 32 -> stride-16 access patterns become bank-uniform
__device__ __forceinline__ int phys(int i) { return i + (i >> 5); }

// ================= fused stats reduction =================
struct Stats {
    float mx, mn, sm, sq;
    int np, nv, p0, va, vb, vl;   // va,vb = two smallest valley idx; vl = last valley
};

__device__ __forceinline__ void stats_combine(Stats &s, const Stats &o) {
    s.mx = fmaxf(s.mx, o.mx);
    s.mn = fminf(s.mn, o.mn);
    s.sm += o.sm; s.sq += o.sq;
    s.np += o.np; s.nv += o.nv;
    s.p0 = min(s.p0, o.p0);
    int m1 = min(s.va, o.va);
    int m2 = min(max(s.va, o.va), min(s.vb, o.vb));
    s.va = m1; s.vb = m2;
    s.vl = max(s.vl, o.vl);
}

__device__ __forceinline__ void stats_warp_reduce(Stats &s) {
    #pragma unroll
    for (int o = 16; o > 0; o >>= 1) {
        Stats t;
        t.mx = __shfl_down_sync(0xffffffffu, s.mx, o);
        t.mn = __shfl_down_sync(0xffffffffu, s.mn, o);
        t.sm = __shfl_down_sync(0xffffffffu, s.sm, o);
        t.sq = __shfl_down_sync(0xffffffffu, s.sq, o);
        t.np = __shfl_down_sync(0xffffffffu, s.np, o);
        t.nv = __shfl_down_sync(0xffffffffu, s.nv, o);
        t.p0 = __shfl_down_sync(0xffffffffu, s.p0, o);
        t.va = __shfl_down_sync(0xffffffffu, s.va, o);
        t.vb = __shfl_down_sync(0xffffffffu, s.vb, o);
        t.vl = __shfl_down_sync(0xffffffffu, s.vl, o);
        stats_combine(s, t);
    }
}

__device__ void stats_block_reduce(Stats &s, float (*rf)[8], int (*ri)[8]) {
    const int lane = threadIdx.x & 31, wid = threadIdx.x >> 5;
    stats_warp_reduce(s);
    __syncthreads();
    if (lane == 0) {
        rf[wid][0] = s.mx; rf[wid][1] = s.mn; rf[wid][2] = s.sm; rf[wid][3] = s.sq;
        ri[wid][0] = s.np; ri[wid][1] = s.nv; ri[wid][2] = s.p0;
        ri[wid][3] = s.va; ri[wid][4] = s.vb; ri[wid][5] = s.vl;
    }
    __syncthreads();
    if (wid == 0) {
        Stats t;
        if (lane < NWARPS) {
            t.mx = rf[lane][0]; t.mn = rf[lane][1]; t.sm = rf[lane][2]; t.sq = rf[lane][3];
            t.np = ri[lane][0]; t.nv = ri[lane][1]; t.p0 = ri[lane][2];
            t.va = ri[lane][3]; t.vb = ri[lane][4]; t.vl = ri[lane][5];
        } else {
            t.mx = -FLT_MAX; t.mn = FLT_MAX; t.sm = 0.0f; t.sq = 0.0f;
            t.np = 0; t.nv = 0; t.p0 = NSIG; t.va = NSIG; t.vb = NSIG; t.vl = -1;
        }
        stats_warp_reduce(t);
        if (lane == 0) {
            rf[0][0] = t.mx; rf[0][1] = t.mn; rf[0][2] = t.sm; rf[0][3] = t.sq;
            ri[0][0] = t.np; ri[0][1] = t.nv; ri[0][2] = t.p0;
            ri[0][3] = t.va; ri[0][4] = t.vb; ri[0][5] = t.vl;
        }
    }
    __syncthreads();
    s.mx = rf[0][0]; s.mn = rf[0][1]; s.sm = rf[0][2]; s.sq = rf[0][3];
    s.np = ri[0][0]; s.nv = ri[0][1]; s.p0 = ri[0][2];
    s.va = ri[0][3]; s.vb = ri[0][4]; s.vl = ri[0][5];
}

// ================= fused pass-3 reduction (3 sums + min + max) =================
__device__ void p3_block_reduce(float &pa, float &a2, float &a1, int &li, int &rx,
                                float (*rf)[8], int (*ri)[8]) {
    const int lane = threadIdx.x & 31, wid = threadIdx.x >> 5;
    #pragma unroll
    for (int o = 16; o > 0; o >>= 1) {
        pa += __shfl_down_sync(0xffffffffu, pa, o);
        a2 += __shfl_down_sync(0xffffffffu, a2, o);
        a1 += __shfl_down_sync(0xffffffffu, a1, o);
        li = min(li, __shfl_down_sync(0xffffffffu, li, o));
        rx = max(rx, __shfl_down_sync(0xffffffffu, rx, o));
    }
    __syncthreads();
    if (lane == 0) {
        rf[wid][0] = pa; rf[wid][1] = a2; rf[wid][2] = a1;
        ri[wid][0] = li; ri[wid][1] = rx;
    }
    __syncthreads();
    if (wid == 0) {
        float tpa = (lane < NWARPS) ? rf[lane][0] : 0.0f;
        float ta2 = (lane < NWARPS) ? rf[lane][1] : 0.0f;
        float ta1 = (lane < NWARPS) ? rf[lane][2] : 0.0f;
        int   tli = (lane < NWARPS) ? ri[lane][0] : NSIG;
        int   trx = (lane < NWARPS) ? ri[lane][1] : -1;
        #pragma unroll
        for (int o = 16; o > 0; o >>= 1) {
            tpa += __shfl_down_sync(0xffffffffu, tpa, o);
            ta2 += __shfl_down_sync(0xffffffffu, ta2, o);
            ta1 += __shfl_down_sync(0xffffffffu, ta1, o);
            tli = min(tli, __shfl_down_sync(0xffffffffu, tli, o));
            trx = max(trx, __shfl_down_sync(0xffffffffu, trx, o));
        }
        if (lane == 0) {
            rf[0][0] = tpa; rf[0][1] = ta2; rf[0][2] = ta1;
            ri[0][0] = tli; ri[0][1] = trx;
        }
    }
    __syncthreads();
    pa = rf[0][0]; a2 = rf[0][1]; a1 = rf[0][2];
    li = ri[0][0]; rx = ri[0][1];
}

// ================= fused 2-sum reduction =================
__device__ void sum2_block_reduce(float &a, float &b, float (*rf)[8]) {
    const int lane = threadIdx.x & 31, wid = threadIdx.x >> 5;
    #pragma unroll
    for (int o = 16; o > 0; o >>= 1) {
        a += __shfl_down_sync(0xffffffffu, a, o);
        b += __shfl_down_sync(0xffffffffu, b, o);
    }
    __syncthreads();
    if (lane == 0) { rf[wid][0] = a; rf[wid][1] = b; }
    __syncthreads();
    if (wid == 0) {
        float ta = (lane < NWARPS) ? rf[lane][0] : 0.0f;
        float tb = (lane < NWARPS) ? rf[lane][1] : 0.0f;
        #pragma unroll
        for (int o = 16; o > 0; o >>= 1) {
            ta += __shfl_down_sync(0xffffffffu, ta, o);
            tb += __shfl_down_sync(0xffffffffu, tb, o);
        }
        if (lane == 0) { rf[0][0] = ta; rf[0][1] = tb; }
    }
    __syncthreads();
    a = rf[0][0]; b = rf[0][1];
}

// ================= radix-8 DIF round (3 stages fused, halves 4h,2h,h) =================
template<int H8>
__device__ __forceinline__ void radix8_round(float2* __restrict__ cf, int tid) {
    const int h = H8 / 4;
    const float scale = -(float)M_PI / (float)(4 * h);
    #pragma unroll
    for (int jj = 0; jj < 2; ++jj) {
        const int j = tid + jj * NTHR;
        const int pos = j & (h - 1);
        const int base = ((j & ~(h - 1)) << 3) + pos;

        float sn, cs;
        __sincosf(scale * (float)pos, &sn, &cs);   // W = e^{-i pi pos/(4h)}
        const float W2r = cs * cs - sn * sn, W2i = 2.0f * cs * sn;
        const float W4r = W2r * W2r - W2i * W2i, W4i = 2.0f * W2r * W2i;
        const float T1r = CQ * (cs + sn), T1i = CQ * (sn - cs);   // W * e^{-i pi/4}

        float2 X0 = cf[phys(base        )];
        float2 X1 = cf[phys(base +     h)];
        float2 X2 = cf[phys(base + 2 * h)];
        float2 X3 = cf[phys(base + 3 * h)];
        float2 X4 = cf[phys(base + 4 * h)];
        float2 X5 = cf[phys(base + 5 * h)];
        float2 X6 = cf[phys(base + 6 * h)];
        float2 X7 = cf[phys(base + 7 * h)];

        // stage A: half = 4h, twiddle W * e^{-i pi k/4}
        float a0r = X0.x + X4.x, a0i = X0.y + X4.y;
        float t0r = X0.x - X4.x, t0i = X0.y - X4.y;
        float b0r = t0r * cs - t0i * sn, b0i = t0r * sn + t0i * cs;

        float a1r = X1.x + X5.x, a1i = X1.y + X5.y;
        float t1r = X1.x - X5.x, t1i = X1.y - X5.y;
        float b1r = t1r * T1r - t1i * T1i, b1i = t1r * T1i + t1i * T1r;

        float a2r = X2.x + X6.x, a2i = X2.y + X6.y;
        float t2r = X2.x - X6.x, t2i = X2.y - X6.y;
        float b2r = t2r * sn + t2i * cs, b2i = t2i * sn - t2r * cs;   // * (-i W)

        float a3r = X3.x + X7.x, a3i = X3.y + X7.y;
        float t3r = X3.x - X7.x, t3i = X3.y - X7.y;
        float b3r = t3r * T1i + t3i * T1r, b3i = t3i * T1i - t3r * T1r; // * (T1i,-T1r)

        // stage B: half = 2h, twiddles W^2 and -i W^2
        float c0r = a0r + a2r, c0i = a0i + a2i;
        float u2r = a0r - a2r, u2i = a0i - a2i;
        float c2r = u2r * W2r - u2i * W2i, c2i = u2r * W2i + u2i * W2r;
        float c1r = a1r + a3r, c1i = a1i + a3i;
        float u3r = a1r - a3r, u3i = a1i - a3i;
        float c3r = u3r * W2i + u3i * W2r, c3i = u3i * W2i - u3r * W2r;

        float d0r = b0r + b2r, d0i = b0i + b2i;
        float v2r = b0r - b2r, v2i = b0i - b2i;
        float d2r = v2r * W2r - v2i * W2i, d2i = v2r * W2i + v2i * W2r;
        float d1r = b1r + b3r, d1i = b1i + b3i;
        float v3r = b1r - b3r, v3i = b1i - b3i;
        float d3r = v3r * W2i + v3i * W2r, d3i = v3i * W2i - v3r * W2r;

        // stage C: half = h, twiddle W^4
        cf[phys(base)] = make_float2(c0r + c1r, c0i + c1i);
        float e1r = c0r - c1r, e1i = c0i - c1i;
        cf[phys(base + h)] = make_float2(e1r * W4r - e1i * W4i, e1r * W4i + e1i * W4r);
        cf[phys(base + 2 * h)] = make_float2(c2r + c3r, c2i + c3i);
        float e3r = c2r - c3r, e3i = c2i - c3i;
        cf[phys(base + 3 * h)] = make_float2(e3r * W4r - e3i * W4i, e3r * W4i + e3i * W4r);

        cf[phys(base + 4 * h)] = make_float2(d0r + d1r, d0i + d1i);
        float f1r = d0r - d1r, f1i = d0i - d1i;
        cf[phys(base + 5 * h)] = make_float2(f1r * W4r - f1i * W4i, f1r * W4i + f1i * W4r);
        cf[phys(base + 6 * h)] = make_float2(d2r + d3r, d2i + d3i);
        float f3r = d2r - d3r, f3i = d2i - d3i;
        cf[phys(base + 7 * h)] = make_float2(f3r * W4r - f3i * W4i, f3r * W4i + f3i * W4r);
    }
}

// ================= radix-16 DIF round (halves 8,4,2,1; constant twiddles) =========
__device__ __forceinline__ void radix16_round(float2* __restrict__ cf, int tid) {
    const int ci = tid * 16;
    const int pb = phys(ci);     // contiguous 16 float2 at padded base (no 32-crossing)
    float xr[16], xi[16];
    #pragma unroll
    for (int m = 0; m < 16; ++m) {
        float2 p = cf[pb + m];
        xr[m] = p.x; xi[m] = p.y;
    }

    const float E8r[8] = {1.0f,  C8F,  CQ,   S8F,  0.0f, -S8F, -CQ,  -C8F};
    const float E8i[8] = {0.0f, -S8F, -CQ,  -C8F, -1.0f, -C8F, -CQ,  -S8F};
    #pragma unroll
    for (int k = 0; k < 8; ++k) {
        float tr = xr[k] - xr[k + 8], ti = xi[k] - xi[k + 8];
        xr[k] += xr[k + 8]; xi[k] += xi[k + 8];
        xr[k + 8] = tr * E8r[k] - ti * E8i[k];
        xi[k + 8] = tr * E8i[k] + ti * E8r[k];
    }
    const float E4r[4] = {1.0f,  CQ,  0.0f, -CQ};
    const float E4i[4] = {0.0f, -CQ, -1.0f, -CQ};
    #pragma unroll
    for (int g = 0; g < 16; g += 8) {
        #pragma unroll
        for (int k = 0; k < 4; ++k) {
            int a = g + k, b = g + k + 4;
            float tr = xr[a] - xr[b], ti = xi[a] - xi[b];
            xr[a] += xr[b]; xi[a] += xi[b];
            xr[b] = tr * E4r[k] - ti * E4i[k];
            xi[b] = tr * E4i[k] + ti * E4r[k];
        }
    }
    #pragma unroll
    for (int g = 0; g < 16; g += 4) {
        float tr = xr[g] - xr[g + 2], ti = xi[g] - xi[g + 2];
        xr[g] += xr[g + 2]; xi[g] += xi[g + 2];
        xr[g + 2] = tr; xi[g + 2] = ti;
        float ur = xr[g + 1] - xr[g + 3], ui = xi[g + 1] - xi[g + 3];
        xr[g + 1] += xr[g + 3]; xi[g + 1] += xi[g + 3];
        xr[g + 3] = ui; xi[g + 3] = -ur;                     // * (-i)
    }
    #pragma unroll
    for (int g = 0; g < 16; g += 2) {
        float tr = xr[g] - xr[g + 1], ti = xi[g] - xi[g + 1];
        xr[g] += xr[g + 1]; xi[g] += xi[g + 1];
        xr[g + 1] = tr; xi[g + 1] = ti;
    }

    #pragma unroll
    for (int m = 0; m < 16; ++m)
        cf[pb + m] = make_float2(xr[m], xi[m]);
}

// ================= main kernel: one block handles TWO rows =================
__global__ __launch_bounds__(NTHR) void feat_kernel(const float* __restrict__ x,
                                                    float* __restrict__ out) {
    extern __shared__ float2 cf[];    // padded complex array, NSIG + NSIG/32 entries
    __shared__ float s_rf[NWARPS][8];
    __shared__ int   s_ri[NWARPS][8];

    const int tid = threadIdx.x;
    const int r0 = 2 * blockIdx.x;
    const int c = tid * 16;          // per-thread chunk start

    // -------- load both rows -> interleaved complex smem (z = row0 + i*row1) -----
    {
        const float4* G0 = (const float4*)(x + (size_t)r0 * NSIG);
        const float4* G1 = G0 + NSIG / 4;
        #pragma unroll
        for (int m = 0; m < NSIG / 4 / NTHR; ++m) {
            int i4 = tid + m * NTHR;
            float4 a = G0[i4];
            float4 b = G1[i4];
            int ci = 4 * i4;
            int pb = phys(ci);       // 4 consecutive (no 32-boundary crossing)
            cf[pb + 0] = make_float2(a.x, b.x);
            cf[pb + 1] = make_float2(a.y, b.y);
            cf[pb + 2] = make_float2(a.z, b.z);
            cf[pb + 3] = make_float2(a.w, b.w);
        }
    }
    __syncthreads();

    // -------- per-row (non-FFT) features: data from GLOBAL into registers --------
    #pragma unroll 1
    for (int hr = 0; hr < 2; ++hr) {
        const float* g = x + (size_t)(r0 + hr) * NSIG;
        float v[18];
        {
            const float4* S4 = (const float4*)(g + c);
            #pragma unroll
            for (int m = 0; m < 4; ++m) {
                float4 p = S4[m];
                v[4 * m + 1] = p.x; v[4 * m + 2] = p.y; v[4 * m + 3] = p.z; v[4 * m + 4] = p.w;
            }
            v[0]  = (c > 0) ? g[c - 1] : 0.0f;
            v[17] = (c + 16 < NSIG) ? g[c + 16] : 0.0f;
        }

        Stats st;
        st.mx = -FLT_MAX; st.mn = FLT_MAX; st.sm = 0.0f; st.sq = 0.0f;
        st.np = 0; st.nv = 0; st.p0 = NSIG; st.va = NSIG; st.vb = NSIG; st.vl = -1;
        #pragma unroll
        for (int j = 1; j <= 16; ++j) {
            float b = v[j];
            st.mx = fmaxf(st.mx, b);
            st.mn = fminf(st.mn, b);
            st.sm += b;
            st.sq += b * b;
            int i = c + j - 1;
            if (i >= 1 && i <= NSIG - 2) {
                float a = v[j - 1], d = v[j + 1];
                bool pk = (b > a) && (b > d);
                bool vl = (b < a) && (b < d);
                if (pk) { st.np++; st.p0 = min(st.p0, i); }
                if (vl) {
                    st.nv++;
                    if (st.va == NSIG) st.va = i;
                    else if (st.vb == NSIG) st.vb = i;
                    st.vl = i;
                }
            }
        }
        stats_block_reduce(st, s_rf, s_ri);

        float var  = (st.sq - st.sm * st.sm * (1.0f / NSIG)) * (1.0f / (NSIG - 1));
        float stdv = sqrtf(var);
        bool valid = (st.np >= 1) && (st.nv >= 2);

        float PA = 0.0f, A2 = 0.0f, A1 = 0.0f, PH = 0.0f, PWHH = 0.0f;
        if (valid) {
            const int p0 = st.p0, v0 = st.va, v1 = st.vb, vlast = st.vl;
            float2 P = cf[phys(p0)], V = cf[phys(v0)];
            float sp = hr ? P.y : P.x;
            float sv = hr ? V.y : V.x;
            PH = sp - sv;
            float hh = 0.5f * (sp + sv);

            float lPA = 0.0f, lA2 = 0.0f, lA1 = 0.0f;
            int lli = NSIG, lri = -1;
            #pragma unroll
            for (int j = 1; j <= 16; ++j) {
                int i = c + j - 1;
                float b = v[j];
                if (i < NSIG - 1) {
                    float seg = (b + v[j + 1]) * (0.5f * SR_INV);
                    if (i >= v0 && i <= vlast - 2) lPA += seg;
                    if (i >= p0 && i <= v1 - 2)    lA2 += seg;
                    if (i >= v0 && i <= p0 - 2)    lA1 += seg;
                }
                if (b >= hh) {
                    if (i >= v0 && i < p0)  lli = min(lli, i);
                    if (i > v0 && i <= p0)  lri = max(lri, i);
                }
            }
            p3_block_reduce(lPA, lA2, lA1, lli, lri, s_rf, s_ri);
            PA = lPA; A2 = lA2; A1 = lA1;
            if (lli == NSIG) lli = v0;
            if (lri == -1)   lri = p0;
            PWHH = (float)(lri - lli) * SR_INV;
        }

        if (tid == 0) {
            float* o = out + (size_t)(r0 + hr) * 10;
            o[0] = st.mx;
            o[1] = st.mx - st.mn;
            o[2] = var;
            o[3] = stdv;
            // o[4] written after FFT
            o[5] = PA;
            o[6] = A2;
            o[7] = PH;
            o[8] = A1;
            o[9] = PWHH;
        }
        __syncthreads();
    }

    // -------- FFT of z: DIF, natural input, bit-reversed output --------
    radix8_round<4096>(cf, tid);
    __syncthreads();
    radix8_round<512>(cf, tid);
    __syncthreads();
    radix8_round<64>(cf, tid);
    __syncthreads();
    radix16_round(cf, tid);
    __syncthreads();

    // -------- magnitude sums via Hermitian split, half-range (|A_{N-k}|=|A_k|) ----
    // even positions p hold k = brev13(p) < N/2; each contributes weight 2.
    float la = 0.0f, lb = 0.0f;
    #pragma unroll 1
    for (int it = 0; it < NSIG / 2 / NTHR; ++it) {
        int p  = 2 * (tid + it * NTHR);
        int k  = brev13(p);
        int km = (NSIG - k) & (NSIG - 1);
        int q  = brev13(km);
        float2 Z = cf[phys(p)];
        float2 W = cf[phys(q)];
        float ar = Z.x + W.x, ai = Z.y - W.y;
        float br = Z.x - W.x, bi = Z.y + W.y;
        la += sqrtf(ar * ar + ai * ai);    // = 2 * |A_k|
        lb += sqrtf(br * br + bi * bi);    // = 2 * |B_k|
    }
    if (tid == 0) {
        // total = 2*sum_{even p} |.| - |.(k=0)| + |.(k=N/2)|
        float2 Z0 = cf[phys(0)];   // Z[0]
        float2 Z1 = cf[phys(1)];   // Z[N/2]
        la += fabsf(Z1.x) - fabsf(Z0.x);
        lb += fabsf(Z1.y) - fabsf(Z0.y);
    }
    sum2_block_reduce(la, lb, s_rf);
    if (tid == 0) {
        out[(size_t)r0 * 10 + 4]       = la * (1.0f / NSIG);
        out[(size_t)(r0 + 1) * 10 + 4] = lb * (1.0f / NSIG);
    }
}

extern "C" void kernel_launch(void* const* d_in, const int* in_sizes, int n_in,
                              void* d_out, int out_size) {
    const float* x = (const float*)d_in[0];
    float* out = (float*)d_out;

    int rows = in_sizes[0] / NSIG;     // 2048
    int nblocks = rows / 2;            // 1024 (one block per row pair)
    size_t shmem = (NSIG + NSIG / 32) * sizeof(float2);   // 67,584 B (padded)

    cudaFuncSetAttribute(feat_kernel, cudaFuncAttributeMaxDynamicSharedMemorySize,
                         (int)shmem);
    feat_kernel<<<nblocks, NTHR, shmem>>>(x, out);
}

// round 10
// speedup vs baseline: 1.0148x; 1.0148x over previous
#include <cuda_runtime.h>
#include <math.h>
#include <float.h>

#define NSIG   8192
#define NTHR   512
#define NWARPS 16
#define SR_INV (1.0f / 30.0f)
#define CQ   0.70710678118654752f   // cos(pi/4)
#define C8F  0.92387953251128676f   // cos(pi/8)
#define S8F  0.38268343236508977f   // sin(pi/8)

__device__ __forceinline__ int brev13(int x) { return (int)(__brev((unsigned)x) >> 19); }
// padded smem index: +1 float2 per 32 -> stride-16 access patterns become bank-uniform
__device__ __forceinline__ int phys(int i) { return i + (i >> 5); }

// ================= fused stats reduction =================
struct Stats {
    float mx, mn, sm, sq;
    int np, nv, p0, va, vb, vl;   // va,vb = two smallest valley idx; vl = last valley
};

__device__ __forceinline__ void stats_combine(Stats &s, const Stats &o) {
    s.mx = fmaxf(s.mx, o.mx);
    s.mn = fminf(s.mn, o.mn);
    s.sm += o.sm; s.sq += o.sq;
    s.np += o.np; s.nv += o.nv;
    s.p0 = min(s.p0, o.p0);
    int m1 = min(s.va, o.va);
    int m2 = min(max(s.va, o.va), min(s.vb, o.vb));
    s.va = m1; s.vb = m2;
    s.vl = max(s.vl, o.vl);
}

__device__ __forceinline__ void stats_warp_reduce(Stats &s) {
    #pragma unroll
    for (int o = 16; o > 0; o >>= 1) {
        Stats t;
        t.mx = __shfl_down_sync(0xffffffffu, s.mx, o);
        t.mn = __shfl_down_sync(0xffffffffu, s.mn, o);
        t.sm = __shfl_down_sync(0xffffffffu, s.sm, o);
        t.sq = __shfl_down_sync(0xffffffffu, s.sq, o);
        t.np = __shfl_down_sync(0xffffffffu, s.np, o);
        t.nv = __shfl_down_sync(0xffffffffu, s.nv, o);
        t.p0 = __shfl_down_sync(0xffffffffu, s.p0, o);
        t.va = __shfl_down_sync(0xffffffffu, s.va, o);
        t.vb = __shfl_down_sync(0xffffffffu, s.vb, o);
        t.vl = __shfl_down_sync(0xffffffffu, s.vl, o);
        stats_combine(s, t);
    }
}

__device__ void stats_block_reduce(Stats &s, float (*rf)[8], int (*ri)[8]) {
    const int lane = threadIdx.x & 31, wid = threadIdx.x >> 5;
    stats_warp_reduce(s);
    __syncthreads();
    if (lane == 0) {
        rf[wid][0] = s.mx; rf[wid][1] = s.mn; rf[wid][2] = s.sm; rf[wid][3] = s.sq;
        ri[wid][0] = s.np; ri[wid][1] = s.nv; ri[wid][2] = s.p0;
        ri[wid][3] = s.va; ri[wid][4] = s.vb; ri[wid][5] = s.vl;
    }
    __syncthreads();
    if (wid == 0) {
        Stats t;
        if (lane < NWARPS) {
            t.mx = rf[lane][0]; t.mn = rf[lane][1]; t.sm = rf[lane][2]; t.sq = rf[lane][3];
            t.np = ri[lane][0]; t.nv = ri[lane][1]; t.p0 = ri[lane][2];
            t.va = ri[lane][3]; t.vb = ri[lane][4]; t.vl = ri[lane][5];
        } else {
            t.mx = -FLT_MAX; t.mn = FLT_MAX; t.sm = 0.0f; t.sq = 0.0f;
            t.np = 0; t.nv = 0; t.p0 = NSIG; t.va = NSIG; t.vb = NSIG; t.vl = -1;
        }
        stats_warp_reduce(t);
        if (lane == 0) {
            rf[0][0] = t.mx; rf[0][1] = t.mn; rf[0][2] = t.sm; rf[0][3] = t.sq;
            ri[0][0] = t.np; ri[0][1] = t.nv; ri[0][2] = t.p0;
            ri[0][3] = t.va; ri[0][4] = t.vb; ri[0][5] = t.vl;
        }
    }
    __syncthreads();
    s.mx = rf[0][0]; s.mn = rf[0][1]; s.sm = rf[0][2]; s.sq = rf[0][3];
    s.np = ri[0][0]; s.nv = ri[0][1]; s.p0 = ri[0][2];
    s.va = ri[0][3]; s.vb = ri[0][4]; s.vl = ri[0][5];
}

// ================= fused pass-3 reduction (3 sums + min + max) =================
__device__ void p3_block_reduce(float &pa, float &a2, float &a1, int &li, int &rx,
                                float (*rf)[8], int (*ri)[8]) {
    const int lane = threadIdx.x & 31, wid = threadIdx.x >> 5;
    #pragma unroll
    for (int o = 16; o > 0; o >>= 1) {
        pa += __shfl_down_sync(0xffffffffu, pa, o);
        a2 += __shfl_down_sync(0xffffffffu, a2, o);
        a1 += __shfl_down_sync(0xffffffffu, a1, o);
        li = min(li, __shfl_down_sync(0xffffffffu, li, o));
        rx = max(rx, __shfl_down_sync(0xffffffffu, rx, o));
    }
    __syncthreads();
    if (lane == 0) {
        rf[wid][0] = pa; rf[wid][1] = a2; rf[wid][2] = a1;
        ri[wid][0] = li; ri[wid][1] = rx;
    }
    __syncthreads();
    if (wid == 0) {
        float tpa = (lane < NWARPS) ? rf[lane][0] : 0.0f;
        float ta2 = (lane < NWARPS) ? rf[lane][1] : 0.0f;
        float ta1 = (lane < NWARPS) ? rf[lane][2] : 0.0f;
        int   tli = (lane < NWARPS) ? ri[lane][0] : NSIG;
        int   trx = (lane < NWARPS) ? ri[lane][1] : -1;
        #pragma unroll
        for (int o = 16; o > 0; o >>= 1) {
            tpa += __shfl_down_sync(0xffffffffu, tpa, o);
            ta2 += __shfl_down_sync(0xffffffffu, ta2, o);
            ta1 += __shfl_down_sync(0xffffffffu, ta1, o);
            tli = min(tli, __shfl_down_sync(0xffffffffu, tli, o));
            trx = max(trx, __shfl_down_sync(0xffffffffu, trx, o));
        }
        if (lane == 0) {
            rf[0][0] = tpa; rf[0][1] = ta2; rf[0][2] = ta1;
            ri[0][0] = tli; ri[0][1] = trx;
        }
    }
    __syncthreads();
    pa = rf[0][0]; a2 = rf[0][1]; a1 = rf[0][2];
    li = ri[0][0]; rx = ri[0][1];
}

// ================= fused 2-sum reduction =================
__device__ void sum2_block_reduce(float &a, float &b, float (*rf)[8]) {
    const int lane = threadIdx.x & 31, wid = threadIdx.x >> 5;
    #pragma unroll
    for (int o = 16; o > 0; o >>= 1) {
        a += __shfl_down_sync(0xffffffffu, a, o);
        b += __shfl_down_sync(0xffffffffu, b, o);
    }
    __syncthreads();
    if (lane == 0) { rf[wid][0] = a; rf[wid][1] = b; }
    __syncthreads();
    if (wid == 0) {
        float ta = (lane < NWARPS) ? rf[lane][0] : 0.0f;
        float tb = (lane < NWARPS) ? rf[lane][1] : 0.0f;
        #pragma unroll
        for (int o = 16; o > 0; o >>= 1) {
            ta += __shfl_down_sync(0xffffffffu, ta, o);
            tb += __shfl_down_sync(0xffffffffu, tb, o);
        }
        if (lane == 0) { rf[0][0] = ta; rf[0][1] = tb; }
    }
    __syncthreads();
    a = rf[0][0]; b = rf[0][1];
}

// ================= radix-8 DIF round (3 stages fused, halves 4h,2h,h) =================
template<int H8>
__device__ __forceinline__ void radix8_round(float2* __restrict__ cf, int tid) {
    const int h = H8 / 4;
    const float scale = -(float)M_PI / (float)(4 * h);
    #pragma unroll
    for (int jj = 0; jj < 2; ++jj) {
        const int j = tid + jj * NTHR;
        const int pos = j & (h - 1);
        const int base = ((j & ~(h - 1)) << 3) + pos;

        float sn, cs;
        __sincosf(scale * (float)pos, &sn, &cs);   // W = e^{-i pi pos/(4h)}
        const float W2r = cs * cs - sn * sn, W2i = 2.0f * cs * sn;
        const float W4r = W2r * W2r - W2i * W2i, W4i = 2.0f * W2r * W2i;
        const float T1r = CQ * (cs + sn), T1i = CQ * (sn - cs);   // W * e^{-i pi/4}

        float2 X0 = cf[phys(base        )];
        float2 X1 = cf[phys(base +     h)];
        float2 X2 = cf[phys(base + 2 * h)];
        float2 X3 = cf[phys(base + 3 * h)];
        float2 X4 = cf[phys(base + 4 * h)];
        float2 X5 = cf[phys(base + 5 * h)];
        float2 X6 = cf[phys(base + 6 * h)];
        float2 X7 = cf[phys(base + 7 * h)];

        // stage A: half = 4h, twiddle W * e^{-i pi k/4}
        float a0r = X0.x + X4.x, a0i = X0.y + X4.y;
        float t0r = X0.x - X4.x, t0i = X0.y - X4.y;
        float b0r = t0r * cs - t0i * sn, b0i = t0r * sn + t0i * cs;

        float a1r = X1.x + X5.x, a1i = X1.y + X5.y;
        float t1r = X1.x - X5.x, t1i = X1.y - X5.y;
        float b1r = t1r * T1r - t1i * T1i, b1i = t1r * T1i + t1i * T1r;

        float a2r = X2.x + X6.x, a2i = X2.y + X6.y;
        float t2r = X2.x - X6.x, t2i = X2.y - X6.y;
        float b2r = t2r * sn + t2i * cs, b2i = t2i * sn - t2r * cs;   // * (-i W)

        float a3r = X3.x + X7.x, a3i = X3.y + X7.y;
        float t3r = X3.x - X7.x, t3i = X3.y - X7.y;
        float b3r = t3r * T1i + t3i * T1r, b3i = t3i * T1i - t3r * T1r; // * (T1i,-T1r)

        // stage B: half = 2h, twiddles W^2 and -i W^2
        float c0r = a0r + a2r, c0i = a0i + a2i;
        float u2r = a0r - a2r, u2i = a0i - a2i;
        float c2r = u2r * W2r - u2i * W2i, c2i = u2r * W2i + u2i * W2r;
        float c1r = a1r + a3r, c1i = a1i + a3i;
        float u3r = a1r - a3r, u3i = a1i - a3i;
        float c3r = u3r * W2i + u3i * W2r, c3i = u3i * W2i - u3r * W2r;

        float d0r = b0r + b2r, d0i = b0i + b2i;
        float v2r = b0r - b2r, v2i = b0i - b2i;
        float d2r = v2r * W2r - v2i * W2i, d2i = v2r * W2i + v2i * W2r;
        float d1r = b1r + b3r, d1i = b1i + b3i;
        float v3r = b1r - b3r, v3i = b1i - b3i;
        float d3r = v3r * W2i + v3i * W2r, d3i = v3i * W2i - v3r * W2r;

        // stage C: half = h, twiddle W^4
        cf[phys(base)] = make_float2(c0r + c1r, c0i + c1i);
        float e1r = c0r - c1r, e1i = c0i - c1i;
        cf[phys(base + h)] = make_float2(e1r * W4r - e1i * W4i, e1r * W4i + e1i * W4r);
        cf[phys(base + 2 * h)] = make_float2(c2r + c3r, c2i + c3i);
        float e3r = c2r - c3r, e3i = c2i - c3i;
        cf[phys(base + 3 * h)] = make_float2(e3r * W4r - e3i * W4i, e3r * W4i + e3i * W4r);

        cf[phys(base + 4 * h)] = make_float2(d0r + d1r, d0i + d1i);
        float f1r = d0r - d1r, f1i = d0i - d1i;
        cf[phys(base + 5 * h)] = make_float2(f1r * W4r - f1i * W4i, f1r * W4i + f1i * W4r);
        cf[phys(base + 6 * h)] = make_float2(d2r + d3r, d2i + d3i);
        float f3r = d2r - d3r, f3i = d2i - d3i;
        cf[phys(base + 7 * h)] = make_float2(f3r * W4r - f3i * W4i, f3r * W4i + f3i * W4r);
    }
}

// ================= radix-16 DIF round (halves 8,4,2,1; constant twiddles) =========
__device__ __forceinline__ void radix16_round(float2* __restrict__ cf, int tid) {
    const int ci = tid * 16;
    const int pb = phys(ci);     // contiguous 16 float2 at padded base (no 32-crossing)
    float xr[16], xi[16];
    #pragma unroll
    for (int m = 0; m < 16; ++m) {
        float2 p = cf[pb + m];
        xr[m] = p.x; xi[m] = p.y;
    }

    const float E8r[8] = {1.0f,  C8F,  CQ,   S8F,  0.0f, -S8F, -CQ,  -C8F};
    const float E8i[8] = {0.0f, -S8F, -CQ,  -C8F, -1.0f, -C8F, -CQ,  -S8F};
    #pragma unroll
    for (int k = 0; k < 8; ++k) {
        float tr = xr[k] - xr[k + 8], ti = xi[k] - xi[k + 8];
        xr[k] += xr[k + 8]; xi[k] += xi[k + 8];
        xr[k + 8] = tr * E8r[k] - ti * E8i[k];
        xi[k + 8] = tr * E8i[k] + ti * E8r[k];
    }
    const float E4r[4] = {1.0f,  CQ,  0.0f, -CQ};
    const float E4i[4] = {0.0f, -CQ, -1.0f, -CQ};
    #pragma unroll
    for (int g = 0; g < 16; g += 8) {
        #pragma unroll
        for (int k = 0; k < 4; ++k) {
            int a = g + k, b = g + k + 4;
            float tr = xr[a] - xr[b], ti = xi[a] - xi[b];
            xr[a] += xr[b]; xi[a] += xi[b];
            xr[b] = tr * E4r[k] - ti * E4i[k];
            xi[b] = tr * E4i[k] + ti * E4r[k];
        }
    }
    #pragma unroll
    for (int g = 0; g < 16; g += 4) {
        float tr = xr[g] - xr[g + 2], ti = xi[g] - xi[g + 2];
        xr[g] += xr[g + 2]; xi[g] += xi[g + 2];
        xr[g + 2] = tr; xi[g + 2] = ti;
        float ur = xr[g + 1] - xr[g + 3], ui = xi[g + 1] - xi[g + 3];
        xr[g + 1] += xr[g + 3]; xi[g + 1] += xi[g + 3];
        xr[g + 3] = ui; xi[g + 3] = -ur;                     // * (-i)
    }
    #pragma unroll
    for (int g = 0; g < 16; g += 2) {
        float tr = xr[g] - xr[g + 1], ti = xi[g] - xi[g + 1];
        xr[g] += xr[g + 1]; xi[g] += xi[g + 1];
        xr[g + 1] = tr; xi[g + 1] = ti;
    }

    #pragma unroll
    for (int m = 0; m < 16; ++m)
        cf[pb + m] = make_float2(xr[m], xi[m]);
}

// ================= main kernel: one block handles TWO rows =================
__global__ __launch_bounds__(NTHR) void feat_kernel(const float* __restrict__ x,
                                                    float* __restrict__ out) {
    extern __shared__ float2 cf[];    // padded complex array, NSIG + NSIG/32 entries
    __shared__ float s_rf[NWARPS][8];
    __shared__ int   s_ri[NWARPS][8];

    const int tid = threadIdx.x;
    const int r0 = 2 * blockIdx.x;
    const int c = tid * 16;          // per-thread chunk start

    // -------- load both rows -> interleaved complex smem (z = row0 + i*row1) -----
    {
        const float4* G0 = (const float4*)(x + (size_t)r0 * NSIG);
        const float4* G1 = G0 + NSIG / 4;
        #pragma unroll
        for (int m = 0; m < NSIG / 4 / NTHR; ++m) {
            int i4 = tid + m * NTHR;
            float4 a = G0[i4];
            float4 b = G1[i4];
            int ci = 4 * i4;
            int pb = phys(ci);       // 4 consecutive (no 32-boundary crossing)
            cf[pb + 0] = make_float2(a.x, b.x);
            cf[pb + 1] = make_float2(a.y, b.y);
            cf[pb + 2] = make_float2(a.z, b.z);
            cf[pb + 3] = make_float2(a.w, b.w);
        }
    }
    __syncthreads();

    // -------- per-row (non-FFT) features: data from GLOBAL into registers --------
    #pragma unroll 1
    for (int hr = 0; hr < 2; ++hr) {
        const float* g = x + (size_t)(r0 + hr) * NSIG;
        float v[18];
        {
            const float4* S4 = (const float4*)(g + c);
            #pragma unroll
            for (int m = 0; m < 4; ++m) {
                float4 p = S4[m];
                v[4 * m + 1] = p.x; v[4 * m + 2] = p.y; v[4 * m + 3] = p.z; v[4 * m + 4] = p.w;
            }
            v[0]  = (c > 0) ? g[c - 1] : 0.0f;
            v[17] = (c + 16 < NSIG) ? g[c + 16] : 0.0f;
        }

        Stats st;
        st.mx = -FLT_MAX; st.mn = FLT_MAX; st.sm = 0.0f; st.sq = 0.0f;
        st.np = 0; st.nv = 0; st.p0 = NSIG; st.va = NSIG; st.vb = NSIG; st.vl = -1;
        #pragma unroll
        for (int j = 1; j <= 16; ++j) {
            float b = v[j];
            st.mx = fmaxf(st.mx, b);
            st.mn = fminf(st.mn, b);
            st.sm += b;
            st.sq += b * b;
            int i = c + j - 1;
            if (i >= 1 && i <= NSIG - 2) {
                float a = v[j - 1], d = v[j + 1];
                bool pk = (b > a) && (b > d);
                bool vl = (b < a) && (b < d);
                if (pk) { st.np++; st.p0 = min(st.p0, i); }
                if (vl) {
                    st.nv++;
                    if (st.va == NSIG) st.va = i;
                    else if (st.vb == NSIG) st.vb = i;
                    st.vl = i;
                }
            }
        }
        stats_block_reduce(st, s_rf, s_ri);

        float var  = (st.sq - st.sm * st.sm * (1.0f / NSIG)) * (1.0f / (NSIG - 1));
        float stdv = sqrtf(var);
        bool valid = (st.np >= 1) && (st.nv >= 2);

        float PA = 0.0f, A2 = 0.0f, A1 = 0.0f, PH = 0.0f, PWHH = 0.0f;
        if (valid) {
            const int p0 = st.p0, v0 = st.va, v1 = st.vb, vlast = st.vl;
            float2 P = cf[phys(p0)], V = cf[phys(v0)];
            float sp = hr ? P.y : P.x;
            float sv = hr ? V.y : V.x;
            PH = sp - sv;
            float hh = 0.5f * (sp + sv);

            float lPA = 0.0f, lA2 = 0.0f, lA1 = 0.0f;
            int lli = NSIG, lri = -1;
            #pragma unroll
            for (int j = 1; j <= 16; ++j) {
                int i = c + j - 1;
                float b = v[j];
                if (i < NSIG - 1) {
                    float seg = (b + v[j + 1]) * (0.5f * SR_INV);
                    if (i >= v0 && i <= vlast - 2) lPA += seg;
                    if (i >= p0 && i <= v1 - 2)    lA2 += seg;
                    if (i >= v0 && i <= p0 - 2)    lA1 += seg;
                }
                if (b >= hh) {
                    if (i >= v0 && i < p0)  lli = min(lli, i);
                    if (i > v0 && i <= p0)  lri = max(lri, i);
                }
            }
            p3_block_reduce(lPA, lA2, lA1, lli, lri, s_rf, s_ri);
            PA = lPA; A2 = lA2; A1 = lA1;
            if (lli == NSIG) lli = v0;
            if (lri == -1)   lri = p0;
            PWHH = (float)(lri - lli) * SR_INV;
        }

        if (tid == 0) {
            float* o = out + (size_t)(r0 + hr) * 10;
            o[0] = st.mx;
            o[1] = st.mx - st.mn;
            o[2] = var;
            o[3] = stdv;
            // o[4] written after FFT
            o[5] = PA;
            o[6] = A2;
            o[7] = PH;
            o[8] = A1;
            o[9] = PWHH;
        }
        __syncthreads();
    }

    // -------- FFT of z: DIF, natural input, bit-reversed output --------
    radix8_round<4096>(cf, tid);
    __syncthreads();
    radix8_round<512>(cf, tid);
    __syncthreads();
    radix8_round<64>(cf, tid);
    __syncthreads();
    radix16_round(cf, tid);
    __syncthreads();

    // -------- magnitude sums via Hermitian split, half-range (|A_{N-k}|=|A_k|) ----
    // even positions p hold k = brev13(p) < N/2; each contributes weight 2.
    float la = 0.0f, lb = 0.0f;
    #pragma unroll 1
    for (int it = 0; it < NSIG / 2 / NTHR; ++it) {
        int p  = 2 * (tid + it * NTHR);
        int k  = brev13(p);
        int km = (NSIG - k) & (NSIG - 1);
        int q  = brev13(km);
        float2 Z = cf[phys(p)];
        float2 W = cf[phys(q)];
        float ar = Z.x + W.x, ai = Z.y - W.y;
        float br = Z.x - W.x, bi = Z.y + W.y;
        la += sqrtf(ar * ar + ai * ai);    // = 2 * |A_k|
        lb += sqrtf(br * br + bi * bi);    // = 2 * |B_k|
    }
    if (tid == 0) {
        // total = 2*sum_{even p} |.| - |.(k=0)| + |.(k=N/2)|
        float2 Z0 = cf[phys(0)];   // Z[0]
        float2 Z1 = cf[phys(1)];   // Z[N/2]
        la += fabsf(Z1.x) - fabsf(Z0.x);
        lb += fabsf(Z1.y) - fabsf(Z0.y);
    }
    sum2_block_reduce(la, lb, s_rf);
    if (tid == 0) {
        out[(size_t)r0 * 10 + 4]       = la * (1.0f / NSIG);
        out[(size_t)(r0 + 1) * 10 + 4] = lb * (1.0f / NSIG);
    }
}

extern "C" void kernel_launch(void* const* d_in, const int* in_sizes, int n_in,
                              void* d_out, int out_size) {
    const float* x = (const float*)d_in[0];
    float* out = (float*)d_out;

    int rows = in_sizes[0] / NSIG;     // 2048
    int nblocks = rows / 2;            // 1024 (one block per row pair)
    size_t shmem = (NSIG + NSIG / 32) * sizeof(float2);   // 67,584 B (padded)

    cudaFuncSetAttribute(feat_kernel, cudaFuncAttributeMaxDynamicSharedMemorySize,
                         (int)shmem);
    feat_kernel<<<nblocks, NTHR, shmem>>>(x, out);
}